// round 9
// baseline (speedup 1.0000x reference)
#include <cuda_runtime.h>
#include <cuda_bf16.h>

#define NUM_CLASSES 601
#define OUT_DIM 27
#define PAD_DIM 32          // pad rows to 32 floats = 128 B = exactly one L1 line
#define NBLOCKS 1184        // 148 SMs x 8 CTAs -> exactly one wave
#define NTHREADS 256        // 8 warps/CTA

// Precomputed softmax table: 601 rows x 32 floats (cols 27..31 = 0 padding).
// 601*32*4 = 76,928 B -> L1/L2 resident.
__device__ __align__(128) float g_table[NUM_CLASSES * PAD_DIM];

// ---------------------------------------------------------------------------
// Kernel A: build softmax table. One warp per class row.
// Matches reference exactly: probs = exp(logits) / sum(exp(logits)).
// ---------------------------------------------------------------------------
__global__ void softmax_table_kernel(const float* __restrict__ W) {
    int r = blockIdx.x;          // 0..600
    int c = threadIdx.x;         // 0..31
    float e = 0.0f;
    if (c < OUT_DIM) {
        e = expf(W[r * OUT_DIM + c]);
    }
    float s = e;
    #pragma unroll
    for (int off = 16; off > 0; off >>= 1)
        s += __shfl_xor_sync(0xffffffffu, s, off);
    g_table[r * PAD_DIM + c] = (c < OUT_DIM) ? (e / s) : 0.0f;
}

// ---------------------------------------------------------------------------
// Kernel B: persistent warp-cooperative gather (grid-stride over 32-row chunks).
// Per chunk of 32 consecutive output rows:
//   - 1 coalesced LDG for the 32 indices
//   - per row: broadcast index via shfl, all lanes read ONE 128B table line
//     (1 L1 wavefront), lanes 0..26 stream-store the 27 output floats.
// Exactly one wave of CTAs -> no wave-transition overhead, loads stay in
// flight continuously across chunks.
// ---------------------------------------------------------------------------
__global__ void __launch_bounds__(NTHREADS) gather_warp_kernel(
    const int* __restrict__ idx, float* __restrict__ out, int batch)
{
    const int lane = threadIdx.x & 31;
    const int gwarp = (blockIdx.x * (NTHREADS / 32)) + (threadIdx.x >> 5);
    const int nwarps = NBLOCKS * (NTHREADS / 32);
    const int nchunks = (batch + 31) >> 5;           // 32-row chunks

    for (int c = gwarp; c < nchunks; c += nwarps) {
        const long long base = (long long)c << 5;
        const long long nrows = (long long)batch - base;   // >= 1

        int myidx = 0;
        if (base + lane < batch) myidx = __ldg(idx + base + lane);

        float* orow = out + base * OUT_DIM + lane;

        if (nrows >= 32) {
            #pragma unroll
            for (int j = 0; j < 32; j++) {
                int rj = __shfl_sync(0xffffffffu, myidx, j);
                float v = g_table[rj * PAD_DIM + lane];
                if (lane < OUT_DIM) __stcs(orow + j * OUT_DIM, v);
            }
        } else {
            for (int j = 0; j < (int)nrows; j++) {
                int rj = __shfl_sync(0xffffffffu, myidx, j);
                float v = g_table[rj * PAD_DIM + lane];
                if (lane < OUT_DIM) __stcs(orow + j * OUT_DIM, v);
            }
        }
    }
}

extern "C" void kernel_launch(void* const* d_in, const int* in_sizes, int n_in,
                              void* d_out, int out_size) {
    const int* idx;
    const float* W;
    int batch;
    if (in_sizes[0] == NUM_CLASSES * OUT_DIM) {
        W = (const float*)d_in[0];
        idx = (const int*)d_in[1];
        batch = in_sizes[1];
    } else {
        idx = (const int*)d_in[0];
        W = (const float*)d_in[1];
        batch = in_sizes[0];
    }

    softmax_table_kernel<<<NUM_CLASSES, 32>>>(W);
    gather_warp_kernel<<<NBLOCKS, NTHREADS>>>(idx, (float*)d_out, batch);
}

// round 10
// speedup vs baseline: 1.1135x; 1.1135x over previous
#include <cuda_runtime.h>
#include <cuda_bf16.h>

#define NUM_CLASSES 601
#define OUT_DIM 27
#define PAD_DIM 32          // pad rows to 32 floats = 128 B = exactly one L1 line

// Precomputed softmax table: 601 rows x 32 floats (cols 27..31 = 0 padding).
// 601*32*4 = 76,928 B -> L1/L2 resident.
__device__ __align__(128) float g_table[NUM_CLASSES * PAD_DIM];

// ---------------------------------------------------------------------------
// Kernel A: build softmax table. One warp per class row.
// Matches reference exactly: probs = exp(logits) / sum(exp(logits)).
// ---------------------------------------------------------------------------
__global__ void softmax_table_kernel(const float* __restrict__ W) {
    int r = blockIdx.x;          // 0..600
    int c = threadIdx.x;         // 0..31
    float e = 0.0f;
    if (c < OUT_DIM) {
        e = expf(W[r * OUT_DIM + c]);
    }
    float s = e;
    #pragma unroll
    for (int off = 16; off > 0; off >>= 1)
        s += __shfl_xor_sync(0xffffffffu, s, off);
    g_table[r * PAD_DIM + c] = (c < OUT_DIM) ? (e / s) : 0.0f;
}

// ---------------------------------------------------------------------------
// Kernel B: warp-cooperative gather, 64 rows per warp, one chunk per warp.
// (R7 structure — the huge grid of short-lived warps is the latency hider;
//  the persistent variant regressed. Chunk doubled 32->64 to halve the
//  per-chunk idx-load latency exposure and widen the MLP window.)
// Per 64-row chunk:
//   - 2 coalesced LDGs fetch the 64 indices
//   - per row: broadcast index via shfl, all lanes read ONE 128B table line
//     (1 L1 wavefront), lanes 0..26 store the 27 output floats (~1.84 wf).
// ---------------------------------------------------------------------------
__global__ void __launch_bounds__(256) gather_warp_kernel(
    const int* __restrict__ idx, float* __restrict__ out, int batch)
{
    const int lane = threadIdx.x & 31;
    const int warp = threadIdx.x >> 5;
    const long long base = ((long long)blockIdx.x * 8 + warp) * 64;
    if (base >= batch) return;

    const long long nrows = batch - base;   // >= 1

    if (nrows >= 64) {
        // fast path: full 64-row chunk
        int i0 = __ldg(idx + base + lane);
        int i1 = __ldg(idx + base + 32 + lane);

        float* orow = out + base * OUT_DIM + lane;

        #pragma unroll
        for (int j = 0; j < 32; j++) {
            int rj = __shfl_sync(0xffffffffu, i0, j);
            float v = g_table[rj * PAD_DIM + lane];
            if (lane < OUT_DIM) orow[j * OUT_DIM] = v;
        }
        orow += 32 * OUT_DIM;
        #pragma unroll
        for (int j = 0; j < 32; j++) {
            int rj = __shfl_sync(0xffffffffu, i1, j);
            float v = g_table[rj * PAD_DIM + lane];
            if (lane < OUT_DIM) orow[j * OUT_DIM] = v;
        }
    } else {
        // tail: up to 63 rows, 32 at a time
        for (long long b = base; b < batch; b += 32) {
            int mi = 0;
            if (b + lane < batch) mi = __ldg(idx + b + lane);
            float* orow = out + b * OUT_DIM + lane;
            int n = (int)((batch - b) < 32 ? (batch - b) : 32);
            for (int j = 0; j < n; j++) {
                int rj = __shfl_sync(0xffffffffu, mi, j);
                float v = g_table[rj * PAD_DIM + lane];
                if (lane < OUT_DIM) orow[j * OUT_DIM] = v;
            }
        }
    }
}

extern "C" void kernel_launch(void* const* d_in, const int* in_sizes, int n_in,
                              void* d_out, int out_size) {
    const int* idx;
    const float* W;
    int batch;
    if (in_sizes[0] == NUM_CLASSES * OUT_DIM) {
        W = (const float*)d_in[0];
        idx = (const int*)d_in[1];
        batch = in_sizes[1];
    } else {
        idx = (const int*)d_in[0];
        W = (const float*)d_in[1];
        batch = in_sizes[0];
    }

    softmax_table_kernel<<<NUM_CLASSES, 32>>>(W);

    // 8 warps/block, 64 rows/warp -> 512 rows per block
    long long nblocks = ((long long)batch + 511) / 512;
    gather_warp_kernel<<<(int)nblocks, 256>>>(idx, (float*)d_out, batch);
}